// round 4
// baseline (speedup 1.0000x reference)
#include <cuda_runtime.h>

#define NG    64
#define NN    2048
#define F     128
#define H     4
#define SPLIT 16
#define CHUNK 128
#define TB    128
#define PST   132            // v[128] + s at [128], padded

typedef unsigned long long u64;

__device__ float g_wa[H*F];
__device__ float g_part[NG*SPLIT*H*PST];
__device__ int   g_flag;          // wa-ready counter (0..4)
__device__ int   g_gcnt[NG];      // per-group finished-chunk counters
__device__ int   g_done;          // finished-group counter

__device__ __forceinline__ u64 ffma2(u64 a, u64 b, u64 c) {
    u64 d;
    asm("fma.rn.f32x2 %0, %1, %2, %3;" : "=l"(d) : "l"(a), "l"(b), "l"(c));
    return d;
}
__device__ __forceinline__ float2 u2f(u64 v) {
    float2 r;
    asm("mov.b64 {%0,%1}, %2;" : "=f"(r.x), "=f"(r.y) : "l"(v));
    return r;
}

// smem layout (bytes)
#define SX_OFF   0                      // 128 rows x 128 floats (xor-swizzled)   65536
#define SWA_OFF  65536                  // wa[4][128]                              2048
#define PP_OFF   67584                  // pp[128][4] (p per row, 4 heads)         2048
#define RED_OFF  69632                  // swred[4 warps][4 heads]                   64
#define BC_OFF   69696                  // broadcast int                              4
#define SMEM_SZ  69760

__global__ void __launch_bounds__(TB) gat_fused(
        const float* __restrict__ feat,
        const float* __restrict__ W1, const float* __restrict__ a1,
        const float* __restrict__ W2, const float* __restrict__ a2,
        const float* __restrict__ W3, const float* __restrict__ a3,
        const float* __restrict__ W4, const float* __restrict__ a4,
        const float* __restrict__ Wo, float* __restrict__ out) {
    extern __shared__ char smem[];
    float*      s_sx  = (float*)(smem + SX_OFF);
    ulonglong2* s_sx2 = (ulonglong2*)(smem + SX_OFF);
    float*      s_wa  = (float*)(smem + SWA_OFF);
    ulonglong2* s_wa2 = (ulonglong2*)(smem + SWA_OFF);
    float4*     s_pp4 = (float4*)(smem + PP_OFF);
    float*      s_red = (float*)(smem + RED_OFF);
    int*        s_bc  = (int*)(smem + BC_OFF);

    const int bid = blockIdx.x;
    const int grp = bid >> 4, chunk = bid & 15;
    const int t = threadIdx.x, lane = t & 31, w = t >> 5;

    // ---- producers: CTAs 0..3 compute wa for head=bid ----------------------
    if (bid < H) {
        const float* W = (bid == 0) ? W1 : (bid == 1) ? W2 : (bid == 2) ? W3 : W4;
        const float* A = (bid == 0) ? a1 : (bid == 1) ? a2 : (bid == 2) ? a3 : a4;
        float4 av = *reinterpret_cast<const float4*>(A + lane*4);
        #pragma unroll 8
        for (int rr = 0; rr < 32; rr++) {
            int i = w*32 + rr;
            float4 wv = *reinterpret_cast<const float4*>(W + i*F + lane*4);
            float d = wv.x*av.x + wv.y*av.y + wv.z*av.z + wv.w*av.w;
            #pragma unroll
            for (int off = 16; off; off >>= 1)
                d += __shfl_xor_sync(0xffffffffu, d, off);
            if (lane == 0) g_wa[bid*F + i] = d;
        }
        __threadfence();
        __syncthreads();
        if (t == 0) atomicAdd(&g_flag, 1);
    }

    // ---- P0: stage this CTA's 128-row chunk into xor-swizzled smem ---------
    const float4* src = reinterpret_cast<const float4*>(
        feat + ((size_t)grp*NN + (size_t)chunk*CHUNK) * F);
    float4* dst4 = (float4*)(smem + SX_OFF);
    #pragma unroll 8
    for (int k = 0; k < 32; k++) {
        int q = t + k*TB;
        float4 f = src[q];
        int row = q >> 5, c4 = q & 31;
        dst4[row*32 + (c4 ^ (row & 7))] = f;
    }

    // ---- wait for wa, load it into smem ------------------------------------
    if (t == 0) {
        unsigned fv;
        while (true) {
            asm volatile("ld.acquire.gpu.global.u32 %0, [%1];"
                         : "=r"(fv) : "l"((const unsigned*)&g_flag));
            if (fv >= H) break;
            __nanosleep(256);
        }
    }
    __syncthreads();
    __threadfence();
    #pragma unroll
    for (int r = 0; r < H; r++) s_wa[t + r*TB] = g_wa[t + r*TB];
    __syncthreads();

    // ---- P1: thread t = row t; packed-f32x2 dots for 4 heads ---------------
    u64 d2[H] = {0ull, 0ull, 0ull, 0ull};
    {
        const int r7 = t & 7;
        #pragma unroll 8
        for (int j4 = 0; j4 < 32; j4++) {
            ulonglong2 f = s_sx2[t*32 + (j4 ^ r7)];
            #pragma unroll
            for (int h = 0; h < H; h++) {
                ulonglong2 wv = s_wa2[h*32 + j4];
                d2[h] = ffma2(f.x, wv.x, d2[h]);
                d2[h] = ffma2(f.y, wv.y, d2[h]);
            }
        }
    }
    float p[H];
    #pragma unroll
    for (int h = 0; h < H; h++) {
        float2 lh = u2f(d2[h]);
        p[h] = __expf(lh.x + lh.y);      // no max shift: |logit| <~ 20, safe
    }
    s_pp4[t] = make_float4(p[0], p[1], p[2], p[3]);

    // warp-level s partial sums
    float sp[H];
    #pragma unroll
    for (int h = 0; h < H; h++) {
        float v = p[h];
        #pragma unroll
        for (int off = 16; off; off >>= 1)
            v += __shfl_xor_sync(0xffffffffu, v, off);
        sp[h] = v;
    }
    if (lane == 0) {
        #pragma unroll
        for (int h = 0; h < H; h++) s_red[w*H + h] = sp[h];
    }
    __syncthreads();

    float* pb = g_part + (size_t)((grp*SPLIT + chunk) * H) * PST;
    if (t < H)
        pb[t*PST + F] = s_red[0*H+t] + s_red[1*H+t] + s_red[2*H+t] + s_red[3*H+t];

    // ---- P2: thread t = column t; weighted row-sum per head ----------------
    {
        float a0 = 0.f, a1v = 0.f, a2v = 0.f, a3v = 0.f;
        const int cq = t >> 2, cl = t & 3;
        #pragma unroll 8
        for (int r = 0; r < CHUNK; r++) {
            float4 p4 = s_pp4[r];
            float xv = s_sx[r*F + ((cq ^ (r & 7)) << 2) + cl];
            a0  = fmaf(p4.x, xv, a0);
            a1v = fmaf(p4.y, xv, a1v);
            a2v = fmaf(p4.z, xv, a2v);
            a3v = fmaf(p4.w, xv, a3v);
        }
        pb[0*PST + t] = a0;
        pb[1*PST + t] = a1v;
        pb[2*PST + t] = a2v;
        pb[3*PST + t] = a3v;
    }

    // ---- completion: last CTA of each group runs the epilogue --------------
    __threadfence();
    __syncthreads();
    if (t == 0) {
        int old = atomicAdd(&g_gcnt[grp], 1);
        *s_bc = (old == SPLIT - 1);
    }
    __syncthreads();
    if (!*s_bc) return;
    __threadfence();

    // epilogue smem (sx region is free now)
    float* pooled = (float*)(smem + SX_OFF);          // [4][128]
    float* multi  = (float*)(smem + SX_OFF) + 512;    // [512]
    float* s4     = (float*)(smem + SX_OFF) + 1024;   // [4]

    const float* pg = g_part + (size_t)grp * SPLIT * H * PST;
    if (t < H) {
        float s = 0.f;
        #pragma unroll
        for (int c = 0; c < SPLIT; c++) s += pg[(size_t)(c*H + t)*PST + F];
        s4[t] = 1.0f / s;
    }
    __syncthreads();

    #pragma unroll
    for (int h = 0; h < H; h++) {
        float vv = 0.f;
        #pragma unroll
        for (int c = 0; c < SPLIT; c++) vv += pg[(size_t)(c*H + h)*PST + t];
        pooled[h*F + t] = vv * s4[h];
    }
    __syncthreads();

    // multi[h*128 + t] = pooled[h] . W_h[:, t]
    {
        const float* WH[H] = {W1, W2, W3, W4};
        #pragma unroll
        for (int h = 0; h < H; h++) {
            const float* W = WH[h];
            float acc = 0.f;
            #pragma unroll 8
            for (int i = 0; i < F; i++)
                acc = fmaf(pooled[h*F + i], W[i*F + t], acc);
            multi[h*F + t] = acc;
        }
    }
    __syncthreads();

    if (t < 64) {
        float acc = 0.f;
        #pragma unroll 8
        for (int k = 0; k < H*F; k++)
            acc = fmaf(multi[k], Wo[k*64 + t], acc);
        out[grp*64 + t] = (acc > 0.f) ? acc : expm1f(acc);
    }

    // reset counters for next graph replay
    __threadfence();
    __syncthreads();
    if (t == 0) {
        g_gcnt[grp] = 0;
        int d = atomicAdd(&g_done, 1);
        if (d == NG - 1) { g_flag = 0; g_done = 0; }
    }
}

extern "C" void kernel_launch(void* const* d_in, const int* in_sizes, int n_in,
                              void* d_out, int out_size) {
    const float* feat = (const float*)d_in[0];
    const float* W1   = (const float*)d_in[1];
    const float* a1   = (const float*)d_in[2];
    const float* W2   = (const float*)d_in[3];
    const float* a2   = (const float*)d_in[4];
    const float* W3   = (const float*)d_in[5];
    const float* a3   = (const float*)d_in[6];
    const float* W4   = (const float*)d_in[7];
    const float* a4   = (const float*)d_in[8];
    const float* Wo   = (const float*)d_in[9];
    float* out = (float*)d_out;

    cudaFuncSetAttribute(gat_fused, cudaFuncAttributeMaxDynamicSharedMemorySize, SMEM_SZ);
    gat_fused<<<NG*SPLIT, TB, SMEM_SZ>>>(feat, W1, a1, W2, a2, W3, a3, W4, a4, Wo, out);
}

// round 6
// speedup vs baseline: 1.2410x; 1.2410x over previous
#include <cuda_runtime.h>

#define NG     64
#define NN     2048
#define F      128
#define H      4
#define SPLIT  16
#define NCHUNK (NG*SPLIT)    // 1024 work units
#define CHUNK  128
#define TB     256
#define PST    132           // v[128] + s at [128]
#define GRID1  444           // 148 SM x 3 CTA persistent

typedef unsigned long long u64;

__device__ float g_wa[H*F];
__device__ float g_part[NCHUNK*H*PST];
__device__ int   g_work;
__device__ int   g_gcnt[NG];

__device__ __forceinline__ u64 ffma2(u64 a, u64 b, u64 c) {
    u64 d; asm("fma.rn.f32x2 %0,%1,%2,%3;" : "=l"(d) : "l"(a), "l"(b), "l"(c)); return d;
}
__device__ __forceinline__ u64 addf2(u64 a, u64 b) {
    u64 d; asm("add.rn.f32x2 %0,%1,%2;" : "=l"(d) : "l"(a), "l"(b)); return d;
}
__device__ __forceinline__ u64 dup2(float x) {
    u64 d; asm("mov.b64 %0,{%1,%1};" : "=l"(d) : "f"(x)); return d;
}
__device__ __forceinline__ float2 u2f(u64 v) {
    float2 r; asm("mov.b64 {%0,%1},%2;" : "=f"(r.x), "=f"(r.y) : "l"(v)); return r;
}

// dynamic smem layout (bytes)
#define SX_OFF   0        // 128 rows x 32 float4, xor-swizzled      65536
#define SWA_OFF  65536    // wa[4][128]                               2048
#define PP_OFF   67584    // float4 pp[128]  (p per row, 4 heads)     2048
#define DP_OFF   69632    // float4 scratch[256] (P1 dots / P2 v)     4096
#define RED_OFF  73728    // float2 red[8]                              64
#define BC_OFF   73792    // 2 ints                                      8
#define SMEM_SZ  73856

// ---------------------------------------------------------------------------
// k0: wa per head (blocks 0..3) + counter reset (block 4)
// ---------------------------------------------------------------------------
__global__ void __launch_bounds__(256) k0_wa(
        const float* __restrict__ W1, const float* __restrict__ a1,
        const float* __restrict__ W2, const float* __restrict__ a2,
        const float* __restrict__ W3, const float* __restrict__ a3,
        const float* __restrict__ W4, const float* __restrict__ a4) {
    const int bid = blockIdx.x, t = threadIdx.x;
    if (bid == H) {                       // reset for this graph replay
        if (t < NG) g_gcnt[t] = 0;
        if (t == NG) g_work = 0;
        return;
    }
    const float* W = (bid == 0) ? W1 : (bid == 1) ? W2 : (bid == 2) ? W3 : W4;
    const float* A = (bid == 0) ? a1 : (bid == 1) ? a2 : (bid == 2) ? a3 : a4;
    const int lane = t & 31, w = t >> 5;
    float4 av = *reinterpret_cast<const float4*>(A + lane*4);
    #pragma unroll
    for (int o = 0; o < 16; o++) {
        int i = w*16 + o;
        float4 wv = *reinterpret_cast<const float4*>(W + i*F + lane*4);
        float d = wv.x*av.x + wv.y*av.y + wv.z*av.z + wv.w*av.w;
        #pragma unroll
        for (int off = 16; off; off >>= 1)
            d += __shfl_xor_sync(0xffffffffu, d, off);
        if (lane == 0) g_wa[bid*F + i] = d;
    }
}

// ---------------------------------------------------------------------------
// k1: persistent main pass + last-CTA-per-group epilogue
// ---------------------------------------------------------------------------
__global__ void __launch_bounds__(TB) k1_main(
        const float* __restrict__ feat,
        const float* __restrict__ W1, const float* __restrict__ W2,
        const float* __restrict__ W3, const float* __restrict__ W4,
        const float* __restrict__ Wo, float* __restrict__ out) {
    extern __shared__ char smem[];
    float*      s_sx  = (float*)(smem + SX_OFF);
    float4*     s_sx4 = (float4*)(smem + SX_OFF);
    ulonglong2* s_sx2 = (ulonglong2*)(smem + SX_OFF);
    float*      s_wa  = (float*)(smem + SWA_OFF);
    ulonglong2* s_wa2 = (ulonglong2*)(smem + SWA_OFF);
    float4*     s_pp  = (float4*)(smem + PP_OFF);
    ulonglong2* s_pp2 = (ulonglong2*)(smem + PP_OFF);
    float4*     s_dp  = (float4*)(smem + DP_OFF);
    ulonglong2* s_vp2 = (ulonglong2*)(smem + DP_OFF);
    float2*     s_red = (float2*)(smem + RED_OFF);
    int*        s_bc  = (int*)(smem + BC_OFF);

    const int t = threadIdx.x, lane = t & 31, w = t >> 5;

    // wa into smem once (k0 completed: stream order)
    s_wa[t] = g_wa[t];
    s_wa[t + 256] = g_wa[t + 256];

    for (;;) {
        __syncthreads();                       // protect smem reuse across iterations
        if (t == 0) s_bc[0] = atomicAdd(&g_work, 1);
        __syncthreads();
        const int c = s_bc[0];
        if (c >= NCHUNK) break;
        const int grp = c >> 4;
        float* pb = g_part + (size_t)c * H * PST;

        // ---- P0: stage chunk (128 rows = 4096 float4) into swizzled smem ---
        {
            const float4* src = reinterpret_cast<const float4*>(
                feat + (size_t)c * CHUNK * F);
            #pragma unroll
            for (int k = 0; k < 16; k++) {
                int q = t + k*TB;
                float4 f = src[q];
                int row = q >> 5, c4 = q & 31;
                s_sx4[row*32 + (c4 ^ (row & 7))] = f;
            }
        }
        __syncthreads();

        // ---- P1: 2 threads per row (column halves), f32x2 dots -------------
        {
            const int row = t & 127, half = t >> 7, r7 = row & 7;
            u64 d2[H] = {0ull, 0ull, 0ull, 0ull};
            #pragma unroll 8
            for (int jj = 0; jj < 16; jj++) {
                int j = half*16 + jj;
                ulonglong2 f = s_sx2[row*32 + (j ^ r7)];
                #pragma unroll
                for (int h = 0; h < H; h++) {
                    ulonglong2 wv = s_wa2[h*32 + j];
                    d2[h] = ffma2(f.x, wv.x, d2[h]);
                    d2[h] = ffma2(f.y, wv.y, d2[h]);
                }
            }
            float4 dv;
            { float2 a0 = u2f(d2[0]), a1 = u2f(d2[1]), a2 = u2f(d2[2]), a3 = u2f(d2[3]);
              dv = make_float4(a0.x+a0.y, a1.x+a1.y, a2.x+a2.y, a3.x+a3.y); }
            s_dp[t] = dv;
        }
        __syncthreads();

        // combine halves, exp, store p; warp-partial sums for s
        {
            const int row = t & 127, hp = t >> 7;   // hp: heads 2hp,2hp+1
            float4 A = s_dp[row], B = s_dp[row + 128];
            float p0, p1;
            if (hp == 0) { p0 = __expf(A.x + B.x); p1 = __expf(A.y + B.y); }
            else         { p0 = __expf(A.z + B.z); p1 = __expf(A.w + B.w); }
            ((float2*)s_pp)[row*2 + hp] = make_float2(p0, p1);
            float s0 = p0, s1 = p1;
            #pragma unroll
            for (int off = 16; off; off >>= 1) {
                s0 += __shfl_xor_sync(0xffffffffu, s0, off);
                s1 += __shfl_xor_sync(0xffffffffu, s1, off);
            }
            if (lane == 0) s_red[w] = make_float2(s0, s1);
        }
        __syncthreads();

        if (t < H) {   // head t: warp range hp*4.., component comp
            int hp = t >> 1, comp = t & 1;
            float s = 0.f;
            #pragma unroll
            for (int ww = 0; ww < 4; ww++) {
                float2 rr = s_red[hp*4 + ww];
                s += comp ? rr.y : rr.x;
            }
            pb[t*PST + F] = s;
        }

        // ---- P2: 2 threads per column (row halves), f32x2 over heads -------
        {
            const int col = t & 127, rhalf = t >> 7;
            const int cq = col >> 2, cl = col & 3;
            u64 a01a = 0ull, a23a = 0ull, a01b = 0ull, a23b = 0ull;
            const int r0 = rhalf * 64;
            #pragma unroll 8
            for (int r = 0; r < 64; r += 2) {
                int ra = r0 + r, rb = ra + 1;
                ulonglong2 pa = s_pp2[ra];
                ulonglong2 pbv = s_pp2[rb];
                u64 xa = dup2(s_sx[ra*F + ((cq ^ (ra & 7)) << 2) + cl]);
                u64 xb = dup2(s_sx[rb*F + ((cq ^ (rb & 7)) << 2) + cl]);
                a01a = ffma2(pa.x, xa, a01a);
                a23a = ffma2(pa.y, xa, a23a);
                a01b = ffma2(pbv.x, xb, a01b);
                a23b = ffma2(pbv.y, xb, a23b);
            }
            ulonglong2 vr;
            vr.x = addf2(a01a, a01b);
            vr.y = addf2(a23a, a23b);
            s_vp2[t] = vr;
        }
        __syncthreads();

        if (t < 128) {
            ulonglong2 A = s_vp2[t], B = s_vp2[t + 128];
            float2 v01 = u2f(addf2(A.x, B.x));
            float2 v23 = u2f(addf2(A.y, B.y));
            pb[0*PST + t] = v01.x;
            pb[1*PST + t] = v01.y;
            pb[2*PST + t] = v23.x;
            pb[3*PST + t] = v23.y;
        }

        // ---- completion + epilogue for the group's last chunk --------------
        __threadfence();
        __syncthreads();
        if (t == 0) {
            int old = atomicAdd(&g_gcnt[grp], 1);
            s_bc[1] = (old == SPLIT - 1);
        }
        __syncthreads();
        if (!s_bc[1]) continue;
        __threadfence();

        {
            float* pooled = s_sx;            // [512]
            float* multi  = s_sx + 512;      // [512]
            float* sinv   = s_sx + 1024;     // [4]
            const float* pg = g_part + (size_t)grp * SPLIT * H * PST;
            if (t < H) {
                float ss = 0.f;
                #pragma unroll
                for (int cc = 0; cc < SPLIT; cc++) ss += pg[(cc*H + t)*PST + F];
                sinv[t] = 1.0f / ss;
            }
            __syncthreads();
            #pragma unroll
            for (int rep = 0; rep < 2; rep++) {
                int o = t + rep*256, h = o >> 7, i = o & 127;
                float vv = 0.f;
                #pragma unroll
                for (int cc = 0; cc < SPLIT; cc++) vv += pg[(cc*H + h)*PST + i];
                pooled[o] = vv * sinv[h];
            }
            __syncthreads();
            {
                #pragma unroll
                for (int rep = 0; rep < 2; rep++) {
                    int o = t + rep*256, h = o >> 7, j = o & 127;
                    const float* Wp = (h == 0) ? W1 : (h == 1) ? W2 : (h == 2) ? W3 : W4;
                    float acc = 0.f;
                    #pragma unroll 8
                    for (int i = 0; i < F; i++)
                        acc = fmaf(pooled[h*F + i], Wp[i*F + j], acc);
                    multi[o] = acc;
                }
            }
            __syncthreads();
            if (t < 64) {
                float acc = 0.f;
                #pragma unroll 8
                for (int k = 0; k < H*F; k++)
                    acc = fmaf(multi[k], Wo[k*64 + t], acc);
                out[grp*64 + t] = (acc > 0.f) ? acc : expm1f(acc);
            }
        }
    }
}

// ---------------------------------------------------------------------------
extern "C" void kernel_launch(void* const* d_in, const int* in_sizes, int n_in,
                              void* d_out, int out_size) {
    const float* feat = (const float*)d_in[0];
    const float* W1   = (const float*)d_in[1];
    const float* a1   = (const float*)d_in[2];
    const float* W2   = (const float*)d_in[3];
    const float* a2   = (const float*)d_in[4];
    const float* W3   = (const float*)d_in[5];
    const float* a3   = (const float*)d_in[6];
    const float* W4   = (const float*)d_in[7];
    const float* a4   = (const float*)d_in[8];
    const float* Wo   = (const float*)d_in[9];
    float* out = (float*)d_out;

    cudaFuncSetAttribute(k1_main, cudaFuncAttributeMaxDynamicSharedMemorySize, SMEM_SZ);
    k0_wa<<<H + 1, 256>>>(W1, a1, W2, a2, W3, a3, W4, a4);
    k1_main<<<GRID1, TB, SMEM_SZ>>>(feat, W1, W2, W3, W4, Wo, out);
}